// round 6
// baseline (speedup 1.0000x reference)
#include <cuda_runtime.h>
#include <mma.h>
#include <math.h>
#include <stdint.h>

using namespace nvcuda;

// Problem constants
#define BSZ 8
#define SEQ 1025
#define SEQP 1152            // padded seq (9*128)
#define KPAD 1088            // 17*64 column coverage used by PV K-loop
#define CH  3200
#define NH  25
#define HD  128
#define MROWS (BSZ*SEQ)      // 8200
#define QKVLD (3*CH)         // 9600
#define BH    (BSZ*NH)       // 200

__device__ __constant__ float kScale = 0.0883883476483184405f; // 1/sqrt(128)

// Scratch (static device globals; allocation-free contract)
__device__ float g_qkv[(size_t)MROWS * QKVLD];          // 315 MB
__device__ float g_attn[(size_t)BH * SEQP * SEQP];      // ~1.06 GB (padded)
__device__ float g_av[(size_t)MROWS * CH];              // 105 MB

typedef wmma::fragment<wmma::matrix_a, 16, 16, 8, wmma::precision::tf32, wmma::row_major> FragA;
typedef wmma::fragment<wmma::matrix_b, 16, 16, 8, wmma::precision::tf32, wmma::row_major> FragB;
typedef wmma::fragment<wmma::matrix_b, 16, 16, 8, wmma::precision::tf32, wmma::col_major> FragBc;
typedef wmma::fragment<wmma::accumulator, 16, 16, 8, float> FragC;

// Dynamic smem layout for pipelined GEMM / PV (bytes):
//   A0 [128][40]  @ 0        (20480)
//   A1 [128][40]  @ 20480
//   B0 [32][136]  @ 40960    (17408)
//   B1 [32][136]  @ 58368
//   Cs [8][16][20]@ 75776    (10240)
#define PIPE_A(buf)  ((float*)(sm + (buf) * 20480))
#define PIPE_B(buf)  ((float*)(sm + 40960 + (buf) * 17408))
#define PIPE_CS      ((float*)(sm + 75776))
#define PIPE_SMEM_BYTES 86016
#define LDA 40
#define LDB 136

// ===========================================================================
// Pipelined tf32 GEMM with bias: C[M,N] = A[M,K] @ B[K,N] + bias[N]
// BM=128, BN=128, BK=32, 2-stage ping-pong. 256 threads = 8 warps (2x4),
// warp tile 64x32. N,K multiples of 128/32; M guarded.
// ===========================================================================
__global__ __launch_bounds__(256) void wgemm_bias(
    const float* __restrict__ A, const float* __restrict__ B,
    const float* __restrict__ bias, float* __restrict__ C,
    int M, int Nn, int K)
{
    extern __shared__ char sm[];

    const int tid = threadIdx.x;
    const int warp = tid >> 5;
    const int lane = tid & 31;
    const int wm = warp >> 2;   // 0..1
    const int wn = warp & 3;    // 0..3
    const int bm = blockIdx.y * 128;
    const int bn = blockIdx.x * 128;

    // Per-thread load coordinates (4 chunks each for A and B)
    int ar[4], ac[4], br[4], bc[4];
    bool aok[4];
#pragma unroll
    for (int p = 0; p < 4; p++) {
        const int ia = tid + p * 256;
        ar[p] = ia >> 3;            // 0..127
        ac[p] = (ia & 7) << 2;      // 0..28
        aok[p] = (bm + ar[p]) < M;
        const int ib = tid + p * 256;
        br[p] = ib >> 5;            // 0..31
        bc[p] = (ib & 31) << 2;     // 0..124
    }

    FragC acc[4][2];
#pragma unroll
    for (int mi = 0; mi < 4; mi++)
#pragma unroll
        for (int ni = 0; ni < 2; ni++) wmma::fill_fragment(acc[mi][ni], 0.0f);

    const int iters = K / 32;

    // Prologue: tile 0 into buffer 0
    {
        float* As = PIPE_A(0);
        float* Bs = PIPE_B(0);
#pragma unroll
        for (int p = 0; p < 4; p++) {
            float4 v = aok[p] ? *(const float4*)(A + (size_t)(bm + ar[p]) * K + ac[p])
                              : make_float4(0.f, 0.f, 0.f, 0.f);
            float4 t;
            t.x = wmma::__float_to_tf32(v.x); t.y = wmma::__float_to_tf32(v.y);
            t.z = wmma::__float_to_tf32(v.z); t.w = wmma::__float_to_tf32(v.w);
            *(float4*)&As[ar[p] * LDA + ac[p]] = t;
        }
#pragma unroll
        for (int p = 0; p < 4; p++) {
            float4 v = *(const float4*)(B + (size_t)br[p] * Nn + bn + bc[p]);
            float4 t;
            t.x = wmma::__float_to_tf32(v.x); t.y = wmma::__float_to_tf32(v.y);
            t.z = wmma::__float_to_tf32(v.z); t.w = wmma::__float_to_tf32(v.w);
            *(float4*)&Bs[br[p] * LDB + bn * 0 + bc[p]] = t;
        }
    }
    __syncthreads();

    for (int it = 0; it < iters; it++) {
        const int cur = it & 1;
        const int nxt = cur ^ 1;
        float* Asc = PIPE_A(cur);
        float* Bsc = PIPE_B(cur);

        // Prefetch next tile into registers (latency hidden behind MMAs)
        float4 an[4], bnv[4];
        const bool have_next = (it + 1) < iters;
        if (have_next) {
            const int k0n = (it + 1) * 32;
#pragma unroll
            for (int p = 0; p < 4; p++)
                an[p] = aok[p] ? *(const float4*)(A + (size_t)(bm + ar[p]) * K + k0n + ac[p])
                               : make_float4(0.f, 0.f, 0.f, 0.f);
#pragma unroll
            for (int p = 0; p < 4; p++)
                bnv[p] = *(const float4*)(B + (size_t)(k0n + br[p]) * Nn + bn + bc[p]);
        }

        // Compute on current buffer
#pragma unroll
        for (int kk = 0; kk < 32; kk += 8) {
            FragA af[4];
            FragB bf[2];
#pragma unroll
            for (int mi = 0; mi < 4; mi++)
                wmma::load_matrix_sync(af[mi], &Asc[(wm * 64 + mi * 16) * LDA + kk], LDA);
#pragma unroll
            for (int ni = 0; ni < 2; ni++)
                wmma::load_matrix_sync(bf[ni], &Bsc[kk * LDB + wn * 32 + ni * 16], LDB);
#pragma unroll
            for (int mi = 0; mi < 4; mi++)
#pragma unroll
                for (int ni = 0; ni < 2; ni++)
                    wmma::mma_sync(acc[mi][ni], af[mi], bf[ni], acc[mi][ni]);
        }

        // Convert + store next tile into alternate buffer
        if (have_next) {
            float* Asn = PIPE_A(nxt);
            float* Bsn = PIPE_B(nxt);
#pragma unroll
            for (int p = 0; p < 4; p++) {
                float4 t;
                t.x = wmma::__float_to_tf32(an[p].x); t.y = wmma::__float_to_tf32(an[p].y);
                t.z = wmma::__float_to_tf32(an[p].z); t.w = wmma::__float_to_tf32(an[p].w);
                *(float4*)&Asn[ar[p] * LDA + ac[p]] = t;
            }
#pragma unroll
            for (int p = 0; p < 4; p++) {
                float4 t;
                t.x = wmma::__float_to_tf32(bnv[p].x); t.y = wmma::__float_to_tf32(bnv[p].y);
                t.z = wmma::__float_to_tf32(bnv[p].z); t.w = wmma::__float_to_tf32(bnv[p].w);
                *(float4*)&Bsn[br[p] * LDB + bc[p]] = t;
            }
        }
        __syncthreads();
    }

    // Epilogue: stage each 16x16 fragment in smem, add bias, guarded store.
    float* Cs = PIPE_CS + warp * (16 * 20);
    const int er = lane >> 1;
    const int ec0 = (lane & 1) * 8;
#pragma unroll
    for (int mi = 0; mi < 4; mi++) {
#pragma unroll
        for (int ni = 0; ni < 2; ni++) {
            wmma::store_matrix_sync(Cs, acc[mi][ni], 20, wmma::mem_row_major);
            __syncwarp();
            const int gr = bm + wm * 64 + mi * 16 + er;
            const int gc = bn + wn * 32 + ni * 16 + ec0;
            if (gr < M) {
                float* dst = C + (size_t)gr * Nn + gc;
                const float* bp = bias + gc;
#pragma unroll
                for (int c = 0; c < 8; c++) dst[c] = Cs[er * 20 + ec0 + c] + bp[c];
            }
            __syncwarp();
        }
    }
}

// ---------------------------------------------------------------------------
// RMSNorm in place over q (which=0) and k (which=1) slabs of g_qkv.
// ---------------------------------------------------------------------------
__global__ __launch_bounds__(256) void rmsnorm_kernel(
    const float* __restrict__ qw, const float* __restrict__ kw)
{
    const int m = blockIdx.x;
    const int which = blockIdx.y;
    float* p = g_qkv + (size_t)m * QKVLD + (size_t)which * CH;
    const float* w = which ? kw : qw;
    const int tid = threadIdx.x;

    float ss = 0.f;
    for (int c = tid * 4; c < CH; c += 1024) {
        float4 v = *(const float4*)(p + c);
        ss += v.x * v.x + v.y * v.y + v.z * v.z + v.w * v.w;
    }
    __shared__ float red[8];
#pragma unroll
    for (int o = 16; o > 0; o >>= 1) ss += __shfl_xor_sync(0xffffffffu, ss, o);
    if ((tid & 31) == 0) red[tid >> 5] = ss;
    __syncthreads();
    if (tid < 32) {
        float s = (tid < 8) ? red[tid] : 0.f;
#pragma unroll
        for (int o = 4; o > 0; o >>= 1) s += __shfl_xor_sync(0xffffffffu, s, o);
        if (tid == 0) red[0] = s;
    }
    __syncthreads();
    const float inv = rsqrtf(red[0] * (1.0f / (float)CH) + 1e-6f);
    for (int c = tid * 4; c < CH; c += 1024) {
        float4 v = *(const float4*)(p + c);
        float4 wv = *(const float4*)(w + c);
        v.x = wv.x * (v.x * inv);
        v.y = wv.y * (v.y * inv);
        v.z = wv.z * (v.z * inv);
        v.w = wv.w * (v.w * inv);
        *(float4*)(p + c) = v;
    }
}

// ---------------------------------------------------------------------------
// Scores (tf32 wmma): S[bh,i,j] = sum_d (scale*q[b,i,h,d]) * k[b,j,h,d]
// BM=128 (4 warps), BN=64 (2 warps), warp = 32x32, K=128 in BK=32 steps.
// ---------------------------------------------------------------------------
__global__ __launch_bounds__(256) void attn_scores_wmma()
{
    __shared__ __align__(32) float Qs[128][40];
    __shared__ __align__(32) float Ks[64][40];

    const int bh = blockIdx.z;
    const int b = bh / NH, h = bh % NH;
    const int i0 = blockIdx.y * 128;
    const int j0 = blockIdx.x * 64;
    const int tid = threadIdx.x;
    const int warp = tid >> 5;
    const int wm = warp >> 1;
    const int wn = warp & 1;

    const float* qbase = g_qkv + (size_t)b * SEQ * QKVLD + (size_t)h * HD;
    const float* kbase = qbase + CH;

    FragC acc[2][2];
#pragma unroll
    for (int mi = 0; mi < 2; mi++)
#pragma unroll
        for (int ni = 0; ni < 2; ni++) wmma::fill_fragment(acc[mi][ni], 0.0f);

    const float sc = kScale;
#pragma unroll
    for (int d0 = 0; d0 < HD; d0 += 32) {
#pragma unroll
        for (int idx = tid; idx < 1024; idx += 256) {
            const int r = idx >> 3;
            const int cg = (idx & 7) << 2;
            const int gi = i0 + r;
            float4 v = (gi < SEQ) ? *(const float4*)(qbase + (size_t)gi * QKVLD + d0 + cg)
                                  : make_float4(0.f, 0.f, 0.f, 0.f);
            float4 t;
            t.x = wmma::__float_to_tf32(v.x * sc);
            t.y = wmma::__float_to_tf32(v.y * sc);
            t.z = wmma::__float_to_tf32(v.z * sc);
            t.w = wmma::__float_to_tf32(v.w * sc);
            *(float4*)&Qs[r][cg] = t;
        }
#pragma unroll
        for (int idx = tid; idx < 512; idx += 256) {
            const int r = idx >> 3;
            const int cg = (idx & 7) << 2;
            const int gj = j0 + r;
            float4 v = (gj < SEQ) ? *(const float4*)(kbase + (size_t)gj * QKVLD + d0 + cg)
                                  : make_float4(0.f, 0.f, 0.f, 0.f);
            float4 t;
            t.x = wmma::__float_to_tf32(v.x);
            t.y = wmma::__float_to_tf32(v.y);
            t.z = wmma::__float_to_tf32(v.z);
            t.w = wmma::__float_to_tf32(v.w);
            *(float4*)&Ks[r][cg] = t;
        }
        __syncthreads();
#pragma unroll
        for (int kk = 0; kk < 32; kk += 8) {
            FragA af[2];
            FragBc bf[2];
#pragma unroll
            for (int mi = 0; mi < 2; mi++)
                wmma::load_matrix_sync(af[mi], &Qs[wm * 32 + mi * 16][kk], 40);
#pragma unroll
            for (int ni = 0; ni < 2; ni++)
                wmma::load_matrix_sync(bf[ni], &Ks[wn * 32 + ni * 16][kk], 40);
#pragma unroll
            for (int mi = 0; mi < 2; mi++)
#pragma unroll
                for (int ni = 0; ni < 2; ni++)
                    wmma::mma_sync(acc[mi][ni], af[mi], bf[ni], acc[mi][ni]);
        }
        __syncthreads();
    }

    float* obase = g_attn + (size_t)bh * SEQP * SEQP;
#pragma unroll
    for (int mi = 0; mi < 2; mi++)
#pragma unroll
        for (int ni = 0; ni < 2; ni++) {
            float* dst = obase + (size_t)(i0 + wm * 32 + mi * 16) * SEQP
                         + (j0 + wn * 32 + ni * 16);
            wmma::store_matrix_sync(dst, acc[mi][ni], SEQP, wmma::mem_row_major);
        }
}

// ---------------------------------------------------------------------------
// Row softmax (padded layout). Zeros padded cols [SEQ, KPAD) for PV.
// ---------------------------------------------------------------------------
__global__ __launch_bounds__(256) void softmax_kernel()
{
    const int i = blockIdx.x;
    const int bh = blockIdx.y;
    float* row = g_attn + ((size_t)bh * SEQP + i) * SEQP;
    __shared__ float buf[SEQ];
    __shared__ float red[8];
    const int tid = threadIdx.x;

    float mx = -1e30f;
    for (int j = tid; j < SEQ; j += 256) {
        float v = row[j];
        buf[j] = v;
        mx = fmaxf(mx, v);
    }
#pragma unroll
    for (int o = 16; o > 0; o >>= 1) mx = fmaxf(mx, __shfl_xor_sync(0xffffffffu, mx, o));
    if ((tid & 31) == 0) red[tid >> 5] = mx;
    __syncthreads();
    if (tid < 32) {
        float m = (tid < 8) ? red[tid] : -1e30f;
#pragma unroll
        for (int o = 4; o > 0; o >>= 1) m = fmaxf(m, __shfl_xor_sync(0xffffffffu, m, o));
        if (tid == 0) red[0] = m;
    }
    __syncthreads();
    const float rmax = red[0];
    __syncthreads();

    float s = 0.f;
    for (int j = tid; j < SEQ; j += 256) {
        float e = __expf(buf[j] - rmax);
        buf[j] = e;
        s += e;
    }
#pragma unroll
    for (int o = 16; o > 0; o >>= 1) s += __shfl_xor_sync(0xffffffffu, s, o);
    if ((tid & 31) == 0) red[tid >> 5] = s;
    __syncthreads();
    if (tid < 32) {
        float v = (tid < 8) ? red[tid] : 0.f;
#pragma unroll
        for (int o = 4; o > 0; o >>= 1) v += __shfl_xor_sync(0xffffffffu, v, o);
        if (tid == 0) red[0] = v;
    }
    __syncthreads();
    const float inv = 1.0f / red[0];
    for (int j = tid; j < SEQ; j += 256) row[j] = buf[j] * inv;
    for (int j = SEQ + tid; j < KPAD; j += 256) row[j] = 0.f;
}

// ---------------------------------------------------------------------------
// Pipelined PV (tf32 wmma): av[b,i,h,:] = sum_j P[bh,i,j] * v[b,j,h,:]
// BM=128 (2 warps x 64), BN=128=HD (4 warps x 32), K over KPAD, BK=32,
// 2-stage ping-pong, dynamic smem (same layout as wgemm_bias).
// ---------------------------------------------------------------------------
__global__ __launch_bounds__(256) void attn_pv_wmma()
{
    extern __shared__ char sm[];

    const int bh = blockIdx.y;
    const int b = bh / NH, h = bh % NH;
    const int i0 = blockIdx.x * 128;
    const int tid = threadIdx.x;
    const int warp = tid >> 5;
    const int lane = tid & 31;
    const int wm = warp >> 2;
    const int wn = warp & 3;

    const float* pbase = g_attn + (size_t)bh * SEQP * SEQP;
    const float* vbase = g_qkv + (size_t)b * SEQ * QKVLD + 2 * CH + (size_t)h * HD;

    int ar[4], ac[4], br[4], bc[4];
#pragma unroll
    for (int p = 0; p < 4; p++) {
        const int ia = tid + p * 256;
        ar[p] = ia >> 3;
        ac[p] = (ia & 7) << 2;
        const int ib = tid + p * 256;
        br[p] = ib >> 5;
        bc[p] = (ib & 31) << 2;
    }

    FragC acc[4][2];
#pragma unroll
    for (int mi = 0; mi < 4; mi++)
#pragma unroll
        for (int ni = 0; ni < 2; ni++) wmma::fill_fragment(acc[mi][ni], 0.0f);

    const int iters = KPAD / 32;   // 34

    // Prologue: tile 0
    {
        float* Ps = PIPE_A(0);
        float* Vs = PIPE_B(0);
#pragma unroll
        for (int p = 0; p < 4; p++) {
            float4 v = *(const float4*)(pbase + (size_t)(i0 + ar[p]) * SEQP + ac[p]);
            float4 t;
            t.x = wmma::__float_to_tf32(v.x); t.y = wmma::__float_to_tf32(v.y);
            t.z = wmma::__float_to_tf32(v.z); t.w = wmma::__float_to_tf32(v.w);
            *(float4*)&Ps[ar[p] * LDA + ac[p]] = t;
        }
#pragma unroll
        for (int p = 0; p < 4; p++) {
            const int gj = br[p];
            float4 v = (gj < SEQ) ? *(const float4*)(vbase + (size_t)gj * QKVLD + bc[p])
                                  : make_float4(0.f, 0.f, 0.f, 0.f);
            float4 t;
            t.x = wmma::__float_to_tf32(v.x); t.y = wmma::__float_to_tf32(v.y);
            t.z = wmma::__float_to_tf32(v.z); t.w = wmma::__float_to_tf32(v.w);
            *(float4*)&Vs[br[p] * LDB + bc[p]] = t;
        }
    }
    __syncthreads();

    for (int it = 0; it < iters; it++) {
        const int cur = it & 1;
        const int nxt = cur ^ 1;
        float* Psc = PIPE_A(cur);
        float* Vsc = PIPE_B(cur);

        float4 an[4], bnv[4];
        const bool have_next = (it + 1) < iters;
        if (have_next) {
            const int k0n = (it + 1) * 32;
#pragma unroll
            for (int p = 0; p < 4; p++)
                an[p] = *(const float4*)(pbase + (size_t)(i0 + ar[p]) * SEQP + k0n + ac[p]);
#pragma unroll
            for (int p = 0; p < 4; p++) {
                const int gj = k0n + br[p];
                bnv[p] = (gj < SEQ) ? *(const float4*)(vbase + (size_t)gj * QKVLD + bc[p])
                                    : make_float4(0.f, 0.f, 0.f, 0.f);
            }
        }

#pragma unroll
        for (int kk = 0; kk < 32; kk += 8) {
            FragA af[4];
            FragB bf[2];
#pragma unroll
            for (int mi = 0; mi < 4; mi++)
                wmma::load_matrix_sync(af[mi], &Psc[(wm * 64 + mi * 16) * LDA + kk], LDA);
#pragma unroll
            for (int ni = 0; ni < 2; ni++)
                wmma::load_matrix_sync(bf[ni], &Vsc[kk * LDB + wn * 32 + ni * 16], LDB);
#pragma unroll
            for (int mi = 0; mi < 4; mi++)
#pragma unroll
                for (int ni = 0; ni < 2; ni++)
                    wmma::mma_sync(acc[mi][ni], af[mi], bf[ni], acc[mi][ni]);
        }

        if (have_next) {
            float* Psn = PIPE_A(nxt);
            float* Vsn = PIPE_B(nxt);
#pragma unroll
            for (int p = 0; p < 4; p++) {
                float4 t;
                t.x = wmma::__float_to_tf32(an[p].x); t.y = wmma::__float_to_tf32(an[p].y);
                t.z = wmma::__float_to_tf32(an[p].z); t.w = wmma::__float_to_tf32(an[p].w);
                *(float4*)&Psn[ar[p] * LDA + ac[p]] = t;
            }
#pragma unroll
            for (int p = 0; p < 4; p++) {
                float4 t;
                t.x = wmma::__float_to_tf32(bnv[p].x); t.y = wmma::__float_to_tf32(bnv[p].y);
                t.z = wmma::__float_to_tf32(bnv[p].z); t.w = wmma::__float_to_tf32(bnv[p].w);
                *(float4*)&Vsn[br[p] * LDB + bc[p]] = t;
            }
        }
        __syncthreads();
    }

    float* Cs = PIPE_CS + warp * (16 * 20);
    const int er = lane >> 1;
    const int ec0 = (lane & 1) * 8;
#pragma unroll
    for (int mi = 0; mi < 4; mi++) {
#pragma unroll
        for (int ni = 0; ni < 2; ni++) {
            wmma::store_matrix_sync(Cs, acc[mi][ni], 20, wmma::mem_row_major);
            __syncwarp();
            const int gi = i0 + wm * 64 + mi * 16 + er;
            const int gc = wn * 32 + ni * 16 + ec0;
            if (gi < SEQ) {
                float* dst = g_av + (size_t)(b * SEQ + gi) * CH + (size_t)h * HD + gc;
#pragma unroll
                for (int c = 0; c < 8; c++) dst[c] = Cs[er * 20 + ec0 + c];
            }
            __syncwarp();
        }
    }
}

// ---------------------------------------------------------------------------
// Launch
// ---------------------------------------------------------------------------
extern "C" void kernel_launch(void* const* d_in, const int* in_sizes, int n_in,
                              void* d_out, int out_size)
{
    (void)in_sizes; (void)n_in; (void)out_size;
    const float* x        = (const float*)d_in[0];
    const float* qkv_w    = (const float*)d_in[1];
    const float* qkv_b    = (const float*)d_in[2];
    const float* q_norm_w = (const float*)d_in[3];
    const float* k_norm_w = (const float*)d_in[4];
    const float* proj_w   = (const float*)d_in[5];
    const float* proj_b   = (const float*)d_in[6];
    float* out = (float*)d_out;

    void* p_qkv = nullptr; void* p_av = nullptr;
    cudaGetSymbolAddress(&p_qkv, g_qkv);
    cudaGetSymbolAddress(&p_av, g_av);
    float* qkv = (float*)p_qkv;
    float* av  = (float*)p_av;

    cudaFuncSetAttribute(wgemm_bias, cudaFuncAttributeMaxDynamicSharedMemorySize,
                         PIPE_SMEM_BYTES);
    cudaFuncSetAttribute(attn_pv_wmma, cudaFuncAttributeMaxDynamicSharedMemorySize,
                         PIPE_SMEM_BYTES);

    // 1) qkv = x @ qkv_w + qkv_b : [8200, 9600], K=3200
    {
        dim3 grid(QKVLD / 128, (MROWS + 127) / 128);
        wgemm_bias<<<grid, 256, PIPE_SMEM_BYTES>>>(x, qkv_w, qkv_b, qkv, MROWS, QKVLD, CH);
    }
    // 2) RMSNorm q and k in place
    {
        dim3 grid(MROWS, 2);
        rmsnorm_kernel<<<grid, 256>>>(q_norm_w, k_norm_w);
    }
    // 3) scores into padded g_attn (17 x-tiles of 64 cover 1025..1088 cols)
    {
        dim3 g(17, SEQP / 128, BH);
        attn_scores_wmma<<<g, 256>>>();
    }
    // 4) softmax (+ zero pad cols)
    {
        dim3 grid(SEQ, BH);
        softmax_kernel<<<grid, 256>>>();
    }
    // 5) PV (pipelined)
    {
        dim3 grid(SEQP / 128, BH);
        attn_pv_wmma<<<grid, 256, PIPE_SMEM_BYTES>>>();
    }
    // 6) out = av @ proj_w + proj_b : [8200, 3200], K=3200
    {
        dim3 grid(CH / 128, (MROWS + 127) / 128);
        wgemm_bias<<<grid, 256, PIPE_SMEM_BYTES>>>(av, proj_w, proj_b, out, MROWS, CH, CH);
    }
}

// round 10
// speedup vs baseline: 1.3298x; 1.3298x over previous
#include <cuda_runtime.h>
#include <mma.h>
#include <math.h>
#include <stdint.h>

using namespace nvcuda;

// Problem constants
#define BSZ 8
#define SEQ 1025
#define SEQP 1152            // padded seq (9*128)
#define KPAD 1088            // 17*64 column coverage used by PV K-loop
#define CH  3200
#define NH  25
#define HD  128
#define MROWS (BSZ*SEQ)      // 8200
#define QKVLD (3*CH)         // 9600
#define BH    (BSZ*NH)       // 200

__device__ __constant__ float kScale = 0.0883883476483184405f; // 1/sqrt(128)

// Scratch (static device globals; allocation-free contract)
__device__ float g_qkv[(size_t)MROWS * QKVLD];          // 315 MB
__device__ float g_attn[(size_t)BH * SEQP * SEQP];      // ~1.06 GB (padded)
__device__ float g_av[(size_t)MROWS * CH];              // 105 MB (tf32-rounded by PV)
__device__ float g_xt[(size_t)MROWS * CH];              // tf32(x)
__device__ float g_wt[(size_t)CH * QKVLD];              // tf32(qkv_w)
__device__ float g_pt[(size_t)CH * CH];                 // tf32(proj_w)

typedef wmma::fragment<wmma::matrix_a, 16, 16, 8, wmma::precision::tf32, wmma::row_major> FragA;
typedef wmma::fragment<wmma::matrix_b, 16, 16, 8, wmma::precision::tf32, wmma::row_major> FragB;
typedef wmma::fragment<wmma::matrix_b, 16, 16, 8, wmma::precision::tf32, wmma::col_major> FragBc;
typedef wmma::fragment<wmma::accumulator, 16, 16, 8, float> FragC;

// ---------------------------------------------------------------------------
// cp.async helpers
// ---------------------------------------------------------------------------
__device__ __forceinline__ void cp16(uint32_t dst, const void* src, bool pred) {
    asm volatile("cp.async.cg.shared.global [%0], [%1], 16, %2;"
                 :: "r"(dst), "l"(src), "r"(pred ? 16 : 0));
}
__device__ __forceinline__ void cp_commit() {
    asm volatile("cp.async.commit_group;" ::: "memory");
}
template <int N>
__device__ __forceinline__ void cp_wait() {
    asm volatile("cp.async.wait_group %0;" :: "n"(N) : "memory");
}

// ---------------------------------------------------------------------------
// tf32 rounding pre-pass: out[i] = __float_to_tf32(in[i]), n % 4 == 0
// ---------------------------------------------------------------------------
__global__ __launch_bounds__(256) void tf32_convert(
    const float* __restrict__ in, float* __restrict__ out, size_t n4)
{
    const size_t stride = (size_t)gridDim.x * 256;
    for (size_t i = blockIdx.x * 256 + threadIdx.x; i < n4; i += stride) {
        float4 v = ((const float4*)in)[i];
        float4 t;
        t.x = wmma::__float_to_tf32(v.x);
        t.y = wmma::__float_to_tf32(v.y);
        t.z = wmma::__float_to_tf32(v.z);
        t.w = wmma::__float_to_tf32(v.w);
        ((float4*)out)[i] = t;
    }
}

// ===========================================================================
// cp.async 2-stage tf32 GEMM with bias: C[M,N] = A[M,K] @ B[K,N] + bias[N]
// Inputs A, B must be tf32-rounded already. BM=BN=128, BK=32, 256 threads,
// warp tile 64x32. N,K multiples of 128/32; M guarded via zfill.
// Dynamic smem: A stages 2x[128][40], B stages 2x[32][136]; Cs overlays A0.
// ===========================================================================
#define LDA 40
#define LDB 136
#define SM_A(s) ((s) * 20480)
#define SM_B(s) (40960 + (s) * 17408)
#define GEMM_SMEM 75776

__global__ __launch_bounds__(256) void wgemm_async(
    const float* __restrict__ A, const float* __restrict__ B,
    const float* __restrict__ bias, float* __restrict__ C,
    int M, int Nn, int K)
{
    extern __shared__ char sm[];
    const uint32_t sbase = (uint32_t)__cvta_generic_to_shared(sm);

    const int tid = threadIdx.x;
    const int warp = tid >> 5;
    const int lane = tid & 31;
    const int wm = warp >> 2;   // 0..1
    const int wn = warp & 3;    // 0..3
    const int bm = blockIdx.y * 128;
    const int bn = blockIdx.x * 128;

    // Per-thread cp.async coordinates (4 x 16B chunks each for A and B)
    int ar[4], ac[4], br[4], bc[4];
    bool aok[4];
    uint32_t adst[4], bdst[4];
#pragma unroll
    for (int p = 0; p < 4; p++) {
        const int ia = tid + p * 256;
        ar[p] = ia >> 3;            // 0..127
        ac[p] = (ia & 7) << 2;      // 0..28
        aok[p] = (bm + ar[p]) < M;
        br[p] = ia >> 5;            // 0..31
        bc[p] = (ia & 31) << 2;     // 0..124
        adst[p] = (uint32_t)((ar[p] * LDA + ac[p]) * 4);
        bdst[p] = (uint32_t)((br[p] * LDB + bc[p]) * 4);
    }

    FragC acc[4][2];
#pragma unroll
    for (int mi = 0; mi < 4; mi++)
#pragma unroll
        for (int ni = 0; ni < 2; ni++) wmma::fill_fragment(acc[mi][ni], 0.0f);

    const int iters = K / 32;

    // Prologue: issue tile 0 into stage 0
#pragma unroll
    for (int p = 0; p < 4; p++)
        cp16(sbase + SM_A(0) + adst[p], A + (size_t)(bm + ar[p]) * K + ac[p], aok[p]);
#pragma unroll
    for (int p = 0; p < 4; p++)
        cp16(sbase + SM_B(0) + bdst[p], B + (size_t)br[p] * Nn + bn + bc[p], true);
    cp_commit();

    for (int it = 0; it < iters; it++) {
        const int cur = it & 1;

        if (it + 1 < iters) {
            const int nxt = cur ^ 1;
            const int k0n = (it + 1) * 32;
#pragma unroll
            for (int p = 0; p < 4; p++)
                cp16(sbase + SM_A(nxt) + adst[p],
                     A + (size_t)(bm + ar[p]) * K + k0n + ac[p], aok[p]);
#pragma unroll
            for (int p = 0; p < 4; p++)
                cp16(sbase + SM_B(nxt) + bdst[p],
                     B + (size_t)(k0n + br[p]) * Nn + bn + bc[p], true);
            cp_commit();
            cp_wait<1>();
        } else {
            cp_wait<0>();
        }
        __syncthreads();

        const float* Asc = (const float*)(sm + SM_A(cur));
        const float* Bsc = (const float*)(sm + SM_B(cur));
#pragma unroll
        for (int kk = 0; kk < 32; kk += 8) {
            FragA af[4];
            FragB bf[2];
#pragma unroll
            for (int mi = 0; mi < 4; mi++)
                wmma::load_matrix_sync(af[mi], &Asc[(wm * 64 + mi * 16) * LDA + kk], LDA);
#pragma unroll
            for (int ni = 0; ni < 2; ni++)
                wmma::load_matrix_sync(bf[ni], &Bsc[kk * LDB + wn * 32 + ni * 16], LDB);
#pragma unroll
            for (int mi = 0; mi < 4; mi++)
#pragma unroll
                for (int ni = 0; ni < 2; ni++)
                    wmma::mma_sync(acc[mi][ni], af[mi], bf[ni], acc[mi][ni]);
        }
        __syncthreads();
    }

    // Epilogue: stage fragments via smem (overlay on stage buffers), add bias.
    float* Cs = (float*)sm + warp * (16 * 20);
    const int er = lane >> 1;
    const int ec0 = (lane & 1) * 8;
#pragma unroll
    for (int mi = 0; mi < 4; mi++) {
#pragma unroll
        for (int ni = 0; ni < 2; ni++) {
            wmma::store_matrix_sync(Cs, acc[mi][ni], 20, wmma::mem_row_major);
            __syncwarp();
            const int gr = bm + wm * 64 + mi * 16 + er;
            const int gc = bn + wn * 32 + ni * 16 + ec0;
            if (gr < M) {
                float* dst = C + (size_t)gr * Nn + gc;
                const float* bp = bias + gc;
#pragma unroll
                for (int c = 0; c < 8; c++) dst[c] = Cs[er * 20 + ec0 + c] + bp[c];
            }
            __syncwarp();
        }
    }
}

// ---------------------------------------------------------------------------
// RMSNorm in place over q (which=0) and k (which=1) slabs of g_qkv.
// ---------------------------------------------------------------------------
__global__ __launch_bounds__(256) void rmsnorm_kernel(
    const float* __restrict__ qw, const float* __restrict__ kw)
{
    const int m = blockIdx.x;
    const int which = blockIdx.y;
    float* p = g_qkv + (size_t)m * QKVLD + (size_t)which * CH;
    const float* w = which ? kw : qw;
    const int tid = threadIdx.x;

    float ss = 0.f;
    for (int c = tid * 4; c < CH; c += 1024) {
        float4 v = *(const float4*)(p + c);
        ss += v.x * v.x + v.y * v.y + v.z * v.z + v.w * v.w;
    }
    __shared__ float red[8];
#pragma unroll
    for (int o = 16; o > 0; o >>= 1) ss += __shfl_xor_sync(0xffffffffu, ss, o);
    if ((tid & 31) == 0) red[tid >> 5] = ss;
    __syncthreads();
    if (tid < 32) {
        float s = (tid < 8) ? red[tid] : 0.f;
#pragma unroll
        for (int o = 4; o > 0; o >>= 1) s += __shfl_xor_sync(0xffffffffu, s, o);
        if (tid == 0) red[0] = s;
    }
    __syncthreads();
    const float inv = rsqrtf(red[0] * (1.0f / (float)CH) + 1e-6f);
    for (int c = tid * 4; c < CH; c += 1024) {
        float4 v = *(const float4*)(p + c);
        float4 wv = *(const float4*)(w + c);
        v.x = wv.x * (v.x * inv);
        v.y = wv.y * (v.y * inv);
        v.z = wv.z * (v.z * inv);
        v.w = wv.w * (v.w * inv);
        *(float4*)(p + c) = v;
    }
}

// ---------------------------------------------------------------------------
// Scores (tf32 wmma): S[bh,i,j] = sum_d (scale*q[b,i,h,d]) * k[b,j,h,d]
// ---------------------------------------------------------------------------
__global__ __launch_bounds__(256) void attn_scores_wmma()
{
    __shared__ __align__(32) float Qs[128][40];
    __shared__ __align__(32) float Ks[64][40];

    const int bh = blockIdx.z;
    const int b = bh / NH, h = bh % NH;
    const int i0 = blockIdx.y * 128;
    const int j0 = blockIdx.x * 64;
    const int tid = threadIdx.x;
    const int warp = tid >> 5;
    const int wm = warp >> 1;
    const int wn = warp & 1;

    const float* qbase = g_qkv + (size_t)b * SEQ * QKVLD + (size_t)h * HD;
    const float* kbase = qbase + CH;

    FragC acc[2][2];
#pragma unroll
    for (int mi = 0; mi < 2; mi++)
#pragma unroll
        for (int ni = 0; ni < 2; ni++) wmma::fill_fragment(acc[mi][ni], 0.0f);

    const float sc = kScale;
#pragma unroll
    for (int d0 = 0; d0 < HD; d0 += 32) {
#pragma unroll
        for (int idx = tid; idx < 1024; idx += 256) {
            const int r = idx >> 3;
            const int cg = (idx & 7) << 2;
            const int gi = i0 + r;
            float4 v = (gi < SEQ) ? *(const float4*)(qbase + (size_t)gi * QKVLD + d0 + cg)
                                  : make_float4(0.f, 0.f, 0.f, 0.f);
            float4 t;
            t.x = wmma::__float_to_tf32(v.x * sc);
            t.y = wmma::__float_to_tf32(v.y * sc);
            t.z = wmma::__float_to_tf32(v.z * sc);
            t.w = wmma::__float_to_tf32(v.w * sc);
            *(float4*)&Qs[r][cg] = t;
        }
#pragma unroll
        for (int idx = tid; idx < 512; idx += 256) {
            const int r = idx >> 3;
            const int cg = (idx & 7) << 2;
            const int gj = j0 + r;
            float4 v = (gj < SEQ) ? *(const float4*)(kbase + (size_t)gj * QKVLD + d0 + cg)
                                  : make_float4(0.f, 0.f, 0.f, 0.f);
            float4 t;
            t.x = wmma::__float_to_tf32(v.x);
            t.y = wmma::__float_to_tf32(v.y);
            t.z = wmma::__float_to_tf32(v.z);
            t.w = wmma::__float_to_tf32(v.w);
            *(float4*)&Ks[r][cg] = t;
        }
        __syncthreads();
#pragma unroll
        for (int kk = 0; kk < 32; kk += 8) {
            FragA af[2];
            FragBc bf[2];
#pragma unroll
            for (int mi = 0; mi < 2; mi++)
                wmma::load_matrix_sync(af[mi], &Qs[wm * 32 + mi * 16][kk], 40);
#pragma unroll
            for (int ni = 0; ni < 2; ni++)
                wmma::load_matrix_sync(bf[ni], &Ks[wn * 32 + ni * 16][kk], 40);
#pragma unroll
            for (int mi = 0; mi < 2; mi++)
#pragma unroll
                for (int ni = 0; ni < 2; ni++)
                    wmma::mma_sync(acc[mi][ni], af[mi], bf[ni], acc[mi][ni]);
        }
        __syncthreads();
    }

    float* obase = g_attn + (size_t)bh * SEQP * SEQP;
#pragma unroll
    for (int mi = 0; mi < 2; mi++)
#pragma unroll
        for (int ni = 0; ni < 2; ni++) {
            float* dst = obase + (size_t)(i0 + wm * 32 + mi * 16) * SEQP
                         + (j0 + wn * 32 + ni * 16);
            wmma::store_matrix_sync(dst, acc[mi][ni], SEQP, wmma::mem_row_major);
        }
}

// ---------------------------------------------------------------------------
// Row softmax (padded layout). Zeros padded cols [SEQ, KPAD) for PV.
// ---------------------------------------------------------------------------
__global__ __launch_bounds__(256) void softmax_kernel()
{
    const int i = blockIdx.x;
    const int bh = blockIdx.y;
    float* row = g_attn + ((size_t)bh * SEQP + i) * SEQP;
    __shared__ float buf[SEQ];
    __shared__ float red[8];
    const int tid = threadIdx.x;

    float mx = -1e30f;
    for (int j = tid; j < SEQ; j += 256) {
        float v = row[j];
        buf[j] = v;
        mx = fmaxf(mx, v);
    }
#pragma unroll
    for (int o = 16; o > 0; o >>= 1) mx = fmaxf(mx, __shfl_xor_sync(0xffffffffu, mx, o));
    if ((tid & 31) == 0) red[tid >> 5] = mx;
    __syncthreads();
    if (tid < 32) {
        float m = (tid < 8) ? red[tid] : -1e30f;
#pragma unroll
        for (int o = 4; o > 0; o >>= 1) m = fmaxf(m, __shfl_xor_sync(0xffffffffu, m, o));
        if (tid == 0) red[0] = m;
    }
    __syncthreads();
    const float rmax = red[0];
    __syncthreads();

    float s = 0.f;
    for (int j = tid; j < SEQ; j += 256) {
        float e = __expf(buf[j] - rmax);
        buf[j] = e;
        s += e;
    }
#pragma unroll
    for (int o = 16; o > 0; o >>= 1) s += __shfl_xor_sync(0xffffffffu, s, o);
    if ((tid & 31) == 0) red[tid >> 5] = s;
    __syncthreads();
    if (tid < 32) {
        float v = (tid < 8) ? red[tid] : 0.f;
#pragma unroll
        for (int o = 4; o > 0; o >>= 1) v += __shfl_xor_sync(0xffffffffu, v, o);
        if (tid == 0) red[0] = v;
    }
    __syncthreads();
    const float inv = 1.0f / red[0];
    for (int j = tid; j < SEQ; j += 256) row[j] = buf[j] * inv;
    for (int j = SEQ + tid; j < KPAD; j += 256) row[j] = 0.f;
}

// ---------------------------------------------------------------------------
// PV (tf32 wmma): av[b,i,h,:] = sum_j P[bh,i,j] * v[b,j,h,:]
// Writes tf32-rounded output (consumed by the proj GEMM as-is).
// ---------------------------------------------------------------------------
__global__ __launch_bounds__(256) void attn_pv_wmma()
{
    __shared__ __align__(32) float Ps[128][40];
    __shared__ __align__(32) float Vs[32][136];
    __shared__ __align__(32) float Cs[8][16][20];

    const int bh = blockIdx.y;
    const int b = bh / NH, h = bh % NH;
    const int i0 = blockIdx.x * 128;
    const int tid = threadIdx.x;
    const int warp = tid >> 5;
    const int lane = tid & 31;
    const int wm = warp >> 2;
    const int wn = warp & 3;

    const float* pbase = g_attn + (size_t)bh * SEQP * SEQP;
    const float* vbase = g_qkv + (size_t)b * SEQ * QKVLD + 2 * CH + (size_t)h * HD;

    FragC acc[4][2];
#pragma unroll
    for (int mi = 0; mi < 4; mi++)
#pragma unroll
        for (int ni = 0; ni < 2; ni++) wmma::fill_fragment(acc[mi][ni], 0.0f);

    for (int k0 = 0; k0 < KPAD; k0 += 32) {
#pragma unroll
        for (int idx = tid; idx < 1024; idx += 256) {
            const int r = idx >> 3;
            const int cg = (idx & 7) << 2;
            float4 v = *(const float4*)(pbase + (size_t)(i0 + r) * SEQP + k0 + cg);
            float4 t;
            t.x = wmma::__float_to_tf32(v.x);
            t.y = wmma::__float_to_tf32(v.y);
            t.z = wmma::__float_to_tf32(v.z);
            t.w = wmma::__float_to_tf32(v.w);
            *(float4*)&Ps[r][cg] = t;
        }
#pragma unroll
        for (int idx = tid; idx < 1024; idx += 256) {
            const int r = idx >> 5;
            const int cg = (idx & 31) << 2;
            const int gj = k0 + r;
            float4 v = (gj < SEQ) ? *(const float4*)(vbase + (size_t)gj * QKVLD + cg)
                                  : make_float4(0.f, 0.f, 0.f, 0.f);
            float4 t;
            t.x = wmma::__float_to_tf32(v.x);
            t.y = wmma::__float_to_tf32(v.y);
            t.z = wmma::__float_to_tf32(v.z);
            t.w = wmma::__float_to_tf32(v.w);
            *(float4*)&Vs[r][cg] = t;
        }
        __syncthreads();
#pragma unroll
        for (int kk = 0; kk < 32; kk += 8) {
            FragA af[4];
            FragB bf[2];
#pragma unroll
            for (int mi = 0; mi < 4; mi++)
                wmma::load_matrix_sync(af[mi], &Ps[wm * 64 + mi * 16][kk], 40);
#pragma unroll
            for (int ni = 0; ni < 2; ni++)
                wmma::load_matrix_sync(bf[ni], &Vs[kk][wn * 32 + ni * 16], 136);
#pragma unroll
            for (int mi = 0; mi < 4; mi++)
#pragma unroll
                for (int ni = 0; ni < 2; ni++)
                    wmma::mma_sync(acc[mi][ni], af[mi], bf[ni], acc[mi][ni]);
        }
        __syncthreads();
    }

    const int er = lane >> 1;
    const int ec0 = (lane & 1) * 8;
#pragma unroll
    for (int mi = 0; mi < 4; mi++) {
#pragma unroll
        for (int ni = 0; ni < 2; ni++) {
            wmma::store_matrix_sync(&Cs[warp][0][0], acc[mi][ni], 20, wmma::mem_row_major);
            __syncwarp();
            const int gi = i0 + wm * 64 + mi * 16 + er;
            const int gc = wn * 32 + ni * 16 + ec0;
            if (gi < SEQ) {
                float* dst = g_av + (size_t)(b * SEQ + gi) * CH + (size_t)h * HD + gc;
#pragma unroll
                for (int c = 0; c < 8; c++)
                    dst[c] = wmma::__float_to_tf32(Cs[warp][er][ec0 + c]);
            }
            __syncwarp();
        }
    }
}

// ---------------------------------------------------------------------------
// Launch
// ---------------------------------------------------------------------------
extern "C" void kernel_launch(void* const* d_in, const int* in_sizes, int n_in,
                              void* d_out, int out_size)
{
    (void)in_sizes; (void)n_in; (void)out_size;
    const float* x        = (const float*)d_in[0];
    const float* qkv_w    = (const float*)d_in[1];
    const float* qkv_b    = (const float*)d_in[2];
    const float* q_norm_w = (const float*)d_in[3];
    const float* k_norm_w = (const float*)d_in[4];
    const float* proj_w   = (const float*)d_in[5];
    const float* proj_b   = (const float*)d_in[6];
    float* out = (float*)d_out;

    void *p_qkv, *p_av, *p_xt, *p_wt, *p_pt;
    cudaGetSymbolAddress(&p_qkv, g_qkv);
    cudaGetSymbolAddress(&p_av, g_av);
    cudaGetSymbolAddress(&p_xt, g_xt);
    cudaGetSymbolAddress(&p_wt, g_wt);
    cudaGetSymbolAddress(&p_pt, g_pt);
    float* qkv = (float*)p_qkv;
    float* av  = (float*)p_av;
    float* xt  = (float*)p_xt;
    float* wt  = (float*)p_wt;
    float* pt  = (float*)p_pt;

    cudaFuncSetAttribute(wgemm_async, cudaFuncAttributeMaxDynamicSharedMemorySize,
                         GEMM_SMEM);

    // 0) tf32 rounding pre-passes
    tf32_convert<<<2048, 256>>>(x, xt, (size_t)MROWS * CH / 4);
    tf32_convert<<<2048, 256>>>(qkv_w, wt, (size_t)CH * QKVLD / 4);
    tf32_convert<<<2048, 256>>>(proj_w, pt, (size_t)CH * CH / 4);

    // 1) qkv = x @ qkv_w + qkv_b : [8200, 9600], K=3200 (cp.async pipelined)
    {
        dim3 grid(QKVLD / 128, (MROWS + 127) / 128);
        wgemm_async<<<grid, 256, GEMM_SMEM>>>(xt, wt, qkv_b, qkv, MROWS, QKVLD, CH);
    }
    // 2) RMSNorm q and k in place
    {
        dim3 grid(MROWS, 2);
        rmsnorm_kernel<<<grid, 256>>>(q_norm_w, k_norm_w);
    }
    // 3) scores into padded g_attn (17 x-tiles of 64 cover 1025..1088 cols)
    {
        dim3 g(17, SEQP / 128, BH);
        attn_scores_wmma<<<g, 256>>>();
    }
    // 4) softmax (+ zero pad cols)
    {
        dim3 grid(SEQ, BH);
        softmax_kernel<<<grid, 256>>>();
    }
    // 5) PV (writes tf32-rounded av)
    {
        dim3 grid(SEQP / 128, BH);
        attn_pv_wmma<<<grid, 256>>>();
    }
    // 6) out = av @ proj_w + proj_b : [8200, 3200], K=3200 (cp.async pipelined)
    {
        dim3 grid(CH / 128, (MROWS + 127) / 128);
        wgemm_async<<<grid, 256, GEMM_SMEM>>>(av, pt, proj_b, out, MROWS, CH, CH);
    }
}